// round 4
// baseline (speedup 1.0000x reference)
#include <cuda_runtime.h>
#include <cuda_bf16.h>
#include <cuda_fp16.h>
#include <math.h>

#define NN 100000
#define EE 6400000
#define IN_CH 128
#define SCAN_T 1024

__device__ __forceinline__ unsigned h2u(__half2 h) { return *reinterpret_cast<unsigned*>(&h); }
__device__ __forceinline__ __half2 u2h(unsigned u) { return *reinterpret_cast<__half2*>(&u); }

// ---------------- scratch (static device memory) -----------------------------
// 32B packed record: {as0 f32, as1 f32, h01,h23,h45,h67,h89 half2, pad}
__device__ __align__(32) unsigned g_rec1[NN * 8];
__device__ __align__(32) unsigned g_rec2[NN * 8];  // {as f32, h01..h89 half2, pad×2}
__device__ __align__(16) float g_ad1[NN * 2];
__device__ __align__(16) float g_t1[NN * 10];
__device__ float g_ad2[NN];
__device__ double g_bnsum[10];
__device__ double g_bnsumsq[10];
__device__ float g_scale[10];
__device__ float g_shift[10];
__device__ int g_deg[NN];
__device__ int g_rowstart[NN + 1];
__device__ int g_cur[NN];
__device__ int g_ssrc[EE];
__device__ int g_is64;

__device__ __forceinline__ float lrelu(float v) { return v > 0.f ? v : 0.2f * v; }

// ---------------- K0: init (zero + dtype detect) ------------------------------
__global__ void kinit(const long long* __restrict__ ei) {
    int i = blockIdx.x * blockDim.x + threadIdx.x;
    if (i < NN) g_deg[i] = 0;
    if (i < 10) { g_bnsum[i] = 0.0; g_bnsumsq[i] = 0.0; }
    if (i == 0) {
        int ok = 1;
        for (int k = 0; k < 64; k++) {
            long long v = ei[k];
            if (v < 0 || v >= NN) ok = 0;
        }
        g_is64 = ok;
    }
}

// ---------------- K1h: histogram of dst ---------------------------------------
__global__ void khist(const void* __restrict__ ei) {
    int i = blockIdx.x * blockDim.x + threadIdx.x;
    if (i >= EE) return;
    int d;
    if (g_is64) d = (int)((const long long*)ei)[EE + i];
    else        d = ((const int*)ei)[EE + i];
    atomicAdd(&g_deg[d], 1);
}

// ---------------- single-block scan -------------------------------------------
__global__ void kscan() {
    __shared__ int s[SCAN_T];
    int t = threadIdx.x;
    const int per = (NN + SCAN_T - 1) / SCAN_T;  // 98
    int start = t * per;
    int end = start + per; if (end > NN) end = NN;
    int sum = 0;
    for (int i = start; i < end; i++) sum += g_deg[i];
    s[t] = sum;
    __syncthreads();
#pragma unroll
    for (int o = 1; o < SCAN_T; o <<= 1) {
        int u = (t >= o) ? s[t - o] : 0;
        __syncthreads();
        s[t] += u;
        __syncthreads();
    }
    int off = s[t] - sum;
    for (int i = start; i < end; i++) {
        g_rowstart[i] = off;
        g_cur[i] = off;
        off += g_deg[i];
    }
    if (t == 0) g_rowstart[NN] = EE;
}

// ---------------- scatter src into dst-sorted order ---------------------------
__global__ void kscatter(const void* __restrict__ ei) {
    int i = blockIdx.x * blockDim.x + threadIdx.x;
    if (i >= EE) return;
    int s, d;
    if (g_is64) {
        const long long* p = (const long long*)ei;
        s = (int)p[i];
        d = (int)p[EE + i];
    } else {
        const int* p = (const int*)ei;
        s = p[i];
        d = p[EE + i];
    }
    int pos = atomicAdd(&g_cur[d], 1);
    g_ssrc[pos] = s;
}

// ---------------- K1: layer1 node GEMM (warp per node) ------------------------
__global__ void k1(const float* __restrict__ x, const float* __restrict__ W1,
                   const float* __restrict__ a1s, const float* __restrict__ a1d) {
    int lane = threadIdx.x & 31;
    int node = (blockIdx.x * blockDim.x + threadIdx.x) >> 5;
    if (node >= NN) return;

    float w[4][10];
#pragma unroll
    for (int kk = 0; kk < 4; kk++)
#pragma unroll
        for (int j = 0; j < 10; j++)
            w[kk][j] = __ldg(&W1[(lane * 4 + kk) * 10 + j]);

    float4 xv = *(const float4*)(x + (size_t)node * IN_CH + lane * 4);
    float acc[10];
#pragma unroll
    for (int j = 0; j < 10; j++)
        acc[j] = xv.x * w[0][j] + xv.y * w[1][j] + xv.z * w[2][j] + xv.w * w[3][j];
#pragma unroll
    for (int j = 0; j < 10; j++)
#pragma unroll
        for (int o = 16; o; o >>= 1)
            acc[j] += __shfl_xor_sync(0xffffffffu, acc[j], o);

    if (lane == 0) {
        float as0 = 0.f, as1v = 0.f, ad0 = 0.f, ad1v = 0.f;
#pragma unroll
        for (int c = 0; c < 5; c++) {
            as0  += acc[c]     * a1s[c];
            as1v += acc[5 + c] * a1s[5 + c];
            ad0  += acc[c]     * a1d[c];
            ad1v += acc[5 + c] * a1d[5 + c];
        }
        ((float2*)g_ad1)[node] = make_float2(ad0, ad1v);
        uint4 a, b;
        a.x = __float_as_uint(as0);
        a.y = __float_as_uint(as1v);
        a.z = h2u(__floats2half2_rn(acc[0], acc[1]));
        a.w = h2u(__floats2half2_rn(acc[2], acc[3]));
        b.x = h2u(__floats2half2_rn(acc[4], acc[5]));
        b.y = h2u(__floats2half2_rn(acc[6], acc[7]));
        b.z = h2u(__floats2half2_rn(acc[8], acc[9]));
        b.w = 0u;
        uint4* rp = (uint4*)(g_rec1 + (size_t)node * 8);
        rp[0] = a;
        rp[1] = b;
    }
}

// ---------------- KE1: layer1 edge aggregation (warp per dst) -----------------
__device__ __forceinline__ void acc_edge1(float acc[12], uint4 a, uint4 b,
                                          float adx, float ady) {
    float x0 = __expf(lrelu(__uint_as_float(a.x) + adx));
    float x1 = __expf(lrelu(__uint_as_float(a.y) + ady));
    float2 f01 = __half22float2(u2h(a.z));
    float2 f23 = __half22float2(u2h(a.w));
    float2 f45 = __half22float2(u2h(b.x));
    float2 f67 = __half22float2(u2h(b.y));
    float2 f89 = __half22float2(u2h(b.z));
    acc[0] += x0;          acc[1] += x1;
    acc[2] += x0 * f01.x;  acc[3] += x0 * f01.y;
    acc[4] += x0 * f23.x;  acc[5] += x0 * f23.y;
    acc[6] += x0 * f45.x;  acc[7] += x1 * f45.y;
    acc[8] += x1 * f67.x;  acc[9] += x1 * f67.y;
    acc[10] += x1 * f89.x; acc[11] += x1 * f89.y;
}

__global__ void kedge1(const float* __restrict__ b1) {
    int lane = threadIdx.x & 31;
    int d = (blockIdx.x * blockDim.x + threadIdx.x) >> 5;
    if (d >= NN) return;
    int rs = g_rowstart[d];
    int re = g_rowstart[d + 1];
    float2 ad = ((const float2*)g_ad1)[d];

    float acc[12];
#pragma unroll
    for (int j = 0; j < 12; j++) acc[j] = 0.f;

    if (lane == 0) {  // self loop
        const uint4* rp = (const uint4*)(g_rec1 + (size_t)d * 8);
        acc_edge1(acc, rp[0], rp[1], ad.x, ad.y);
    }
    int j = rs + lane;
    for (; j + 32 < re; j += 64) {
        int s0 = g_ssrc[j];
        int s1 = g_ssrc[j + 32];
        const uint4* p0 = (const uint4*)(g_rec1 + (size_t)s0 * 8);
        const uint4* p1 = (const uint4*)(g_rec1 + (size_t)s1 * 8);
        uint4 a0 = p0[0], b0 = p0[1];
        uint4 a1 = p1[0], b1v = p1[1];
        acc_edge1(acc, a0, b0, ad.x, ad.y);
        acc_edge1(acc, a1, b1v, ad.x, ad.y);
    }
    if (j < re) {
        int s0 = g_ssrc[j];
        const uint4* p0 = (const uint4*)(g_rec1 + (size_t)s0 * 8);
        acc_edge1(acc, p0[0], p0[1], ad.x, ad.y);
    }
#pragma unroll
    for (int k = 0; k < 12; k++)
#pragma unroll
        for (int o = 16; o; o >>= 1)
            acc[k] += __shfl_xor_sync(0xffffffffu, acc[k], o);

    if (lane == 0) {
        float i0 = 1.f / (acc[0] + 1e-16f);
        float i1 = 1.f / (acc[1] + 1e-16f);
        float2* tp = (float2*)(g_t1 + (size_t)d * 10);
        tp[0] = make_float2(acc[2] * i0 + b1[0], acc[3] * i0 + b1[1]);
        tp[1] = make_float2(acc[4] * i0 + b1[2], acc[5] * i0 + b1[3]);
        tp[2] = make_float2(acc[6] * i0 + b1[4], acc[7] * i1 + b1[5]);
        tp[3] = make_float2(acc[8] * i1 + b1[6], acc[9] * i1 + b1[7]);
        tp[4] = make_float2(acc[10] * i1 + b1[8], acc[11] * i1 + b1[9]);
    }
}

// ---------------- KBN: BN statistics ------------------------------------------
__global__ void kbn() {
    __shared__ double ssum[10], ssq[10];
    if (threadIdx.x < 10) { ssum[threadIdx.x] = 0.0; ssq[threadIdx.x] = 0.0; }
    __syncthreads();
    int node = blockIdx.x * blockDim.x + threadIdx.x;
    int lane = threadIdx.x & 31;
    float t[10];
    if (node < NN) {
        const float2* tp = (const float2*)(g_t1 + (size_t)node * 10);
#pragma unroll
        for (int c = 0; c < 5; c++) {
            float2 v = tp[c];
            t[2 * c] = v.x;
            t[2 * c + 1] = v.y;
        }
    } else {
#pragma unroll
        for (int j = 0; j < 10; j++) t[j] = 0.f;
    }
#pragma unroll
    for (int j = 0; j < 10; j++) {
        float v = t[j];
        float s = t[j] * t[j];
#pragma unroll
        for (int o = 16; o; o >>= 1) {
            v += __shfl_xor_sync(0xffffffffu, v, o);
            s += __shfl_xor_sync(0xffffffffu, s, o);
        }
        if (lane == 0) {
            atomicAdd(&ssum[j], (double)v);
            atomicAdd(&ssq[j], (double)s);
        }
    }
    __syncthreads();
    if (threadIdx.x < 10) {
        atomicAdd(&g_bnsum[threadIdx.x], ssum[threadIdx.x]);
        atomicAdd(&g_bnsumsq[threadIdx.x], ssq[threadIdx.x]);
    }
}

// ---------------- K4: BN affine constants -------------------------------------
__global__ void k4(const float* __restrict__ gamma, const float* __restrict__ beta) {
    int j = threadIdx.x;
    if (j < 10) {
        double mean = g_bnsum[j] / (double)NN;
        double var = g_bnsumsq[j] / (double)NN - mean * mean;
        float sc = gamma[j] * (float)rsqrt(var + 1e-5);
        g_scale[j] = sc;
        g_shift[j] = beta[j] - (float)mean * sc;
    }
}

// ---------------- K5: BN + ELU + layer2 node GEMM -----------------------------
__global__ void k5(const float* __restrict__ W2, const float* __restrict__ a2s,
                   const float* __restrict__ a2d) {
    __shared__ float sW[100], sa[10], sd[10], ssc[10], ssh[10];
    if (threadIdx.x < 100) sW[threadIdx.x] = W2[threadIdx.x];
    if (threadIdx.x < 10) {
        sa[threadIdx.x] = a2s[threadIdx.x];
        sd[threadIdx.x] = a2d[threadIdx.x];
        ssc[threadIdx.x] = g_scale[threadIdx.x];
        ssh[threadIdx.x] = g_shift[threadIdx.x];
    }
    __syncthreads();
    int node = blockIdx.x * blockDim.x + threadIdx.x;
    if (node >= NN) return;

    float y[10];
    const float2* tp = (const float2*)(g_t1 + (size_t)node * 10);
#pragma unroll
    for (int c = 0; c < 5; c++) {
        float2 v = tp[c];
        float u0 = v.x * ssc[2 * c] + ssh[2 * c];
        float u1 = v.y * ssc[2 * c + 1] + ssh[2 * c + 1];
        y[2 * c]     = u0 > 0.f ? u0 : expm1f(u0);
        y[2 * c + 1] = u1 > 0.f ? u1 : expm1f(u1);
    }
    float h[10];
#pragma unroll
    for (int c = 0; c < 10; c++) {
        float s = 0.f;
#pragma unroll
        for (int j = 0; j < 10; j++) s += y[j] * sW[j * 10 + c];
        h[c] = s;
    }
    float as = 0.f, ad = 0.f;
#pragma unroll
    for (int c = 0; c < 10; c++) {
        as += h[c] * sa[c];
        ad += h[c] * sd[c];
    }
    g_ad2[node] = ad;
    uint4 a, b;
    a.x = __float_as_uint(as);
    a.y = h2u(__floats2half2_rn(h[0], h[1]));
    a.z = h2u(__floats2half2_rn(h[2], h[3]));
    a.w = h2u(__floats2half2_rn(h[4], h[5]));
    b.x = h2u(__floats2half2_rn(h[6], h[7]));
    b.y = h2u(__floats2half2_rn(h[8], h[9]));
    b.z = 0u; b.w = 0u;
    uint4* rp = (uint4*)(g_rec2 + (size_t)node * 8);
    rp[0] = a;
    rp[1] = b;
}

// ---------------- KE2: layer2 edge aggregation -> output ----------------------
__device__ __forceinline__ void acc_edge2(float acc[11], uint4 a, uint2 b, float ad) {
    float ex = __expf(lrelu(__uint_as_float(a.x) + ad));
    float2 f01 = __half22float2(u2h(a.y));
    float2 f23 = __half22float2(u2h(a.z));
    float2 f45 = __half22float2(u2h(a.w));
    float2 f67 = __half22float2(u2h(b.x));
    float2 f89 = __half22float2(u2h(b.y));
    acc[0] += ex;
    acc[1] += ex * f01.x; acc[2] += ex * f01.y;
    acc[3] += ex * f23.x; acc[4] += ex * f23.y;
    acc[5] += ex * f45.x; acc[6] += ex * f45.y;
    acc[7] += ex * f67.x; acc[8] += ex * f67.y;
    acc[9] += ex * f89.x; acc[10] += ex * f89.y;
}

__global__ void kedge2(float* __restrict__ out, const float* __restrict__ b2) {
    int lane = threadIdx.x & 31;
    int d = (blockIdx.x * blockDim.x + threadIdx.x) >> 5;
    if (d >= NN) return;
    int rs = g_rowstart[d];
    int re = g_rowstart[d + 1];
    float ad = g_ad2[d];

    float acc[11];
#pragma unroll
    for (int j = 0; j < 11; j++) acc[j] = 0.f;

    if (lane == 0) {  // self loop
        const uint4* rp = (const uint4*)(g_rec2 + (size_t)d * 8);
        uint4 a = rp[0];
        uint2 b = *(const uint2*)(rp + 1);
        acc_edge2(acc, a, b, ad);
    }
    int j = rs + lane;
    for (; j + 32 < re; j += 64) {
        int s0 = g_ssrc[j];
        int s1 = g_ssrc[j + 32];
        const uint4* p0 = (const uint4*)(g_rec2 + (size_t)s0 * 8);
        const uint4* p1 = (const uint4*)(g_rec2 + (size_t)s1 * 8);
        uint4 a0 = p0[0];
        uint2 b0 = *(const uint2*)(p0 + 1);
        uint4 a1 = p1[0];
        uint2 b1v = *(const uint2*)(p1 + 1);
        acc_edge2(acc, a0, b0, ad);
        acc_edge2(acc, a1, b1v, ad);
    }
    if (j < re) {
        int s0 = g_ssrc[j];
        const uint4* p0 = (const uint4*)(g_rec2 + (size_t)s0 * 8);
        uint4 a = p0[0];
        uint2 b = *(const uint2*)(p0 + 1);
        acc_edge2(acc, a, b, ad);
    }
#pragma unroll
    for (int k = 0; k < 11; k++)
#pragma unroll
        for (int o = 16; o; o >>= 1)
            acc[k] += __shfl_xor_sync(0xffffffffu, acc[k], o);

    if (lane == 0) {
        float inv = 1.f / (acc[0] + 1e-16f);
        float* op = out + (size_t)d * 10;
#pragma unroll
        for (int c = 0; c < 10; c++)
            op[c] = acc[1 + c] * inv + b2[c];
    }
}

// ---------------- launch -------------------------------------------------------
extern "C" void kernel_launch(void* const* d_in, const int* in_sizes, int n_in,
                              void* d_out, int out_size) {
    (void)in_sizes; (void)n_in; (void)out_size;
    const float* x      = (const float*)d_in[0];
    const float* W1     = (const float*)d_in[1];
    const float* a_src1 = (const float*)d_in[2];
    const float* a_dst1 = (const float*)d_in[3];
    const float* b1     = (const float*)d_in[4];
    const float* gamma1 = (const float*)d_in[5];
    const float* beta1  = (const float*)d_in[6];
    const float* W2     = (const float*)d_in[7];
    const float* a_src2 = (const float*)d_in[8];
    const float* a_dst2 = (const float*)d_in[9];
    const float* b2     = (const float*)d_in[10];
    const void*  ei     = d_in[11];

    kinit<<<(NN + 255) / 256, 256>>>((const long long*)ei);       // 0
    khist<<<(EE + 255) / 256, 256>>>(ei);                         // 1
    kscan<<<1, SCAN_T>>>();                                       // 2
    kscatter<<<(EE + 255) / 256, 256>>>(ei);                      // 3 <- profiled
    k1<<<(NN * 32 + 255) / 256, 256>>>(x, W1, a_src1, a_dst1);    // 4
    kedge1<<<(NN * 32 + 255) / 256, 256>>>(b1);                   // 5
    kbn<<<(NN + 255) / 256, 256>>>();                             // 6
    k4<<<1, 32>>>(gamma1, beta1);                                 // 7
    k5<<<(NN + 255) / 256, 256>>>(W2, a_src2, a_dst2);            // 8
    kedge2<<<(NN * 32 + 255) / 256, 256>>>((float*)d_out, b2);    // 9
}